// round 3
// baseline (speedup 1.0000x reference)
#include <cuda_runtime.h>
#include <math_constants.h>

// ---------------------------------------------------------------------------
// Problem constants (from reference):
//   N = 8192 points, 4 scales:
//     scale0: M=16000, C=32   (voxel size 0.03)
//     scale1: M= 4000, C=64   (voxel size 0.06)
//     scale2: M=  512, C=128  (voxel size 0.12)
//     scale3: M=   64, C=256  (voxel size 0.24)
//   OFFSET = -0.5f*0.015f*64 per axis; center = idx*vs + OFFSET + 0.5*vs
//   out[N, 480] = concat over scales of 3-NN inverse-distance interpolation
// ---------------------------------------------------------------------------

#define NPTS      8192
#define OUTC      480

// segmentation config (compile-time)
#define S0 64
#define S1 32
#define S2 8
#define S3 2
#define SEG0 250   // 16000/64
#define SEG1 125   // 4000/32
#define SEG2 64    // 512/8
#define SEG3 32    // 64/2
#define ROWS 8     // 8192 / (256 threads * 4 points)

// block ranges for the fused partial kernel
#define B0 (ROWS*S0)            // 512
#define B1 (B0 + ROWS*S1)       // 768
#define B2 (B1 + ROWS*S2)       // 832
#define B3 (B2 + ROWS*S3)       // 848

// scratch bases (in DI entries)
#define SB0 0
#define SB1 (NPTS*S0*3)                   // 1572864
#define SB2 (SB1 + NPTS*S1*3)             // 2359296
#define SB3 (SB2 + NPTS*S2*3)             // 2555904
#define SB_TOTAL (SB3 + NPTS*S3*3)        // 2605056  (~20.8 MB)

struct __align__(8) DI { float d; int i; };

__device__ DI g_part[SB_TOTAL];

__device__ __forceinline__ bool diless(float da, int ia, float db, int ib) {
    return (da < db) || (da == db && ia < ib);
}

__device__ __forceinline__ void ins3(float d, int i,
                                     float& d0, int& i0,
                                     float& d1, int& i1,
                                     float& d2, int& i2) {
    if (diless(d, i, d2, i2)) {
        d2 = d; i2 = i;
        if (diless(d2, i2, d1, i1)) { float td = d1; d1 = d2; d2 = td; int ti = i1; i1 = i2; i2 = ti; }
        if (diless(d1, i1, d0, i0)) { float td = d0; d0 = d1; d1 = td; int ti = i0; i0 = i1; i1 = ti; }
    }
}

// ---------------------------------------------------------------------------
// Kernel B: fused partial top-3 over all 4 scales.
// One block = 1024 points (4 per thread, in registers) x one query segment.
// Query tile staged in smem as float4 (xyz center + query index in .w).
// Queries are scanned in increasing index order, and inserts use strict '<',
// so within a thread equal distances keep the lower index — matching
// jax.lax.top_k's stable tie-break for duplicate voxels.
// ---------------------------------------------------------------------------
__global__ void __launch_bounds__(256)
nn_partial(const float* __restrict__ points,
           const int* __restrict__ idx0, const int* __restrict__ idx1,
           const int* __restrict__ idx2, const int* __restrict__ idx3)
{
    __shared__ float4 tile[256];

    int b = blockIdx.x;
    const int* inds; float vs; int S, segLen, sbase, local;
    if (b < B0)      { local = b;      inds = idx0; S = S0; segLen = SEG0; sbase = SB0; vs = 0.015f * 2.0f; }
    else if (b < B1) { local = b - B0; inds = idx1; S = S1; segLen = SEG1; sbase = SB1; vs = 0.015f * 4.0f; }
    else if (b < B2) { local = b - B1; inds = idx2; S = S2; segLen = SEG2; sbase = SB2; vs = 0.015f * 8.0f; }
    else             { local = b - B2; inds = idx3; S = S3; segLen = SEG3; sbase = SB3; vs = 0.015f * 16.0f; }

    // OFFSET computed exactly as numpy float32 does (all ops are exact scalings)
    const float offc = (-0.5f * 0.015f) * 64.0f + 0.5f * vs;

    int row = local / S;
    int seg = local - row * S;
    int t = threadIdx.x;

    float px[4], py[4], pz[4];
    float bd0[4], bd1[4], bd2[4];
    int   bi0[4], bi1[4], bi2[4];
#pragma unroll
    for (int k = 0; k < 4; k++) {
        int p = row * 1024 + t + k * 256;
        px[k] = points[p * 3 + 0];
        py[k] = points[p * 3 + 1];
        pz[k] = points[p * 3 + 2];
        bd0[k] = bd1[k] = bd2[k] = CUDART_INF_F;
        bi0[k] = bi1[k] = bi2[k] = 0x7fffffff;
    }

    int qs = seg * segLen, qe = qs + segLen;
    for (int base = qs; base < qe; base += 256) {
        int cnt = min(256, qe - base);
        __syncthreads();
        if (t < cnt) {
            int4 v = ((const int4*)inds)[base + t];   // [batch, ix, iy, iz]
            tile[t] = make_float4((float)v.y * vs + offc,
                                  (float)v.z * vs + offc,
                                  (float)v.w * vs + offc,
                                  __int_as_float(base + t));
        }
        __syncthreads();

        for (int j = 0; j < cnt; ++j) {
            float4 q = tile[j];
#pragma unroll
            for (int k = 0; k < 4; k++) {
                float dx = px[k] - q.x;
                float dy = py[k] - q.y;
                float dz = pz[k] - q.z;
                float d2 = dx * dx + dy * dy + dz * dz;
                if (d2 < bd2[k]) {                       // strict: stable tie-break
                    int qi = __float_as_int(q.w);
                    bd2[k] = d2; bi2[k] = qi;
                    if (bd2[k] < bd1[k]) { float td = bd1[k]; bd1[k] = bd2[k]; bd2[k] = td;
                                           int ti = bi1[k]; bi1[k] = bi2[k]; bi2[k] = ti; }
                    if (bd1[k] < bd0[k]) { float td = bd0[k]; bd0[k] = bd1[k]; bd1[k] = td;
                                           int ti = bi0[k]; bi0[k] = bi1[k]; bi1[k] = ti; }
                }
            }
        }
    }

#pragma unroll
    for (int k = 0; k < 4; k++) {
        int p = row * 1024 + t + k * 256;
        int o = sbase + (p * S + seg) * 3;
        DI e;
        e.d = bd0[k]; e.i = bi0[k]; g_part[o + 0] = e;
        e.d = bd1[k]; e.i = bi1[k]; g_part[o + 1] = e;
        e.d = bd2[k]; e.i = bi2[k]; g_part[o + 2] = e;
    }
}

// ---------------------------------------------------------------------------
// Kernel C: merge partial top-3 lists (warp shuffle tree, index tie-break),
// compute inverse-distance weights, gather features, write output slice.
// One warp per (scale, point). 4*8192 warps -> 4096 blocks of 256 threads.
// ---------------------------------------------------------------------------
__global__ void __launch_bounds__(256)
merge_gather(const float* __restrict__ f0, const float* __restrict__ f1,
             const float* __restrict__ f2, const float* __restrict__ f3,
             float* __restrict__ out)
{
    int w = (blockIdx.x * 256 + threadIdx.x) >> 5;
    int lane = threadIdx.x & 31;
    int scale = w >> 13;       // /8192
    int n = w & (NPTS - 1);

    const float* f; int S, C, coff, sbase;
    switch (scale) {
        case 0:  f = f0; S = S0; C = 32;  coff = 0;   sbase = SB0; break;
        case 1:  f = f1; S = S1; C = 64;  coff = 32;  sbase = SB1; break;
        case 2:  f = f2; S = S2; C = 128; coff = 96;  sbase = SB2; break;
        default: f = f3; S = S3; C = 256; coff = 224; sbase = SB3; break;
    }

    float d0 = CUDART_INF_F, d1 = CUDART_INF_F, d2 = CUDART_INF_F;
    int   i0 = 0x7fffffff,   i1 = 0x7fffffff,   i2 = 0x7fffffff;

    for (int seg = lane; seg < S; seg += 32) {
        int o = sbase + (n * S + seg) * 3;
        DI e0 = g_part[o], e1 = g_part[o + 1], e2 = g_part[o + 2];
        ins3(e0.d, e0.i, d0, i0, d1, i1, d2, i2);
        ins3(e1.d, e1.i, d0, i0, d1, i1, d2, i2);
        ins3(e2.d, e2.i, d0, i0, d1, i1, d2, i2);
    }

    // shfl_down merge tree; only lane 0's result is consumed, and at each
    // step the lanes it transitively depends on are uncontaminated.
#pragma unroll
    for (int off = 16; off > 0; off >>= 1) {
        float e0 = __shfl_down_sync(0xffffffffu, d0, off);
        float e1 = __shfl_down_sync(0xffffffffu, d1, off);
        float e2 = __shfl_down_sync(0xffffffffu, d2, off);
        int   j0 = __shfl_down_sync(0xffffffffu, i0, off);
        int   j1 = __shfl_down_sync(0xffffffffu, i1, off);
        int   j2 = __shfl_down_sync(0xffffffffu, i2, off);
        ins3(e0, j0, d0, i0, d1, i1, d2, i2);
        ins3(e1, j1, d0, i0, d1, i1, d2, i2);
        ins3(e2, j2, d0, i0, d1, i1, d2, i2);
    }

    // broadcast winner from lane 0
    d0 = __shfl_sync(0xffffffffu, d0, 0);
    d1 = __shfl_sync(0xffffffffu, d1, 0);
    d2 = __shfl_sync(0xffffffffu, d2, 0);
    i0 = __shfl_sync(0xffffffffu, i0, 0);
    i1 = __shfl_sync(0xffffffffu, i1, 0);
    i2 = __shfl_sync(0xffffffffu, i2, 0);

    float r0 = 1.0f / (d0 + 1e-8f);
    float r1 = 1.0f / (d1 + 1e-8f);
    float r2 = 1.0f / (d2 + 1e-8f);
    float inv = 1.0f / (r0 + r1 + r2);
    float w0 = r0 * inv, w1 = r1 * inv, w2 = r2 * inv;

    const float* p0 = f + (size_t)i0 * C;
    const float* p1 = f + (size_t)i1 * C;
    const float* p2 = f + (size_t)i2 * C;
    float* o = out + (size_t)n * OUTC + coff;
    for (int c = lane; c < C; c += 32)
        o[c] = w0 * p0[c] + w1 * p1[c] + w2 * p2[c];
}

// ---------------------------------------------------------------------------
// Launch. Inputs identified by element count (all ten counts distinct, so this
// is robust to metadata ordering):
//   points 24576 | batch_ids 8192 (unused: all-zero, ref ignores batch)
//   indices: 64000 / 16000 / 2048 / 256
//   feats:   512000 / 256000 / 65536 / 16384
// ---------------------------------------------------------------------------
extern "C" void kernel_launch(void* const* d_in, const int* in_sizes, int n_in,
                              void* d_out, int out_size)
{
    const float* points = nullptr;
    const int* idx[4] = {nullptr, nullptr, nullptr, nullptr};
    const float* feats[4] = {nullptr, nullptr, nullptr, nullptr};

    for (int i = 0; i < n_in; i++) {
        switch (in_sizes[i]) {
            case 24576:  points   = (const float*)d_in[i]; break;
            case 64000:  idx[0]   = (const int*)d_in[i];   break;
            case 16000:  idx[1]   = (const int*)d_in[i];   break;
            case 2048:   idx[2]   = (const int*)d_in[i];   break;
            case 256:    idx[3]   = (const int*)d_in[i];   break;
            case 512000: feats[0] = (const float*)d_in[i]; break;
            case 256000: feats[1] = (const float*)d_in[i]; break;
            case 65536:  feats[2] = (const float*)d_in[i]; break;
            case 16384:  feats[3] = (const float*)d_in[i]; break;
            default: break; // batch_ids (8192) unused
        }
    }

    nn_partial<<<B3, 256>>>(points, idx[0], idx[1], idx[2], idx[3]);
    merge_gather<<<(4 * NPTS) / 8, 256>>>(feats[0], feats[1], feats[2], feats[3],
                                          (float*)d_out);
}

// round 4
// speedup vs baseline: 3.9241x; 3.9241x over previous
#include <cuda_runtime.h>
#include <math_constants.h>

// ---------------------------------------------------------------------------
// Exact 3-NN interpolation via grid ring-search.
// Queries are voxel centers on regular grids:
//   scale0: 32^3 grid, M=16000, C=32,  vs=0.03
//   scale1: 16^3 grid, M= 4000, C=64,  vs=0.06
//   scale2:  8^3 grid, M=  512, C=128, vs=0.12
//   scale3:  4^3 grid, M=   64, C=256, vs=0.24
// Occupancy map per cell stores the 3 LOWEST row indices mapping to that cell
// (duplicate voxel rows have identical distance; jax.lax.top_k is stable, so
// lower rows win ties -> per-cell sorted row list + (d2,row) lexicographic
// insertion reproduces the reference selection exactly).
// Ring-search stop rule: after examining all cells with Chebyshev radius <= r,
// any unexamined center is at Euclidean distance >= (r+0.5)*vs from the point
// (point lies inside its own cell). If >=3 rows found strictly inside that
// bound, the global top-3 is already in hand. Terminates at full-grid coverage
// otherwise.
// ---------------------------------------------------------------------------

#define NPTS  8192
#define OUTC  480
#define INF_I 0x7fffffff

// occupancy map layout (int4 per cell: 3 sorted row slots + pad)
#define MB0 0
#define MB1 32768
#define MB2 (32768 + 4096)
#define MB3 (32768 + 4096 + 512)
#define MCELLS (32768 + 4096 + 512 + 64)

__device__ int4 g_map[MCELLS];

// ---------------------------------------------------------------------------
__global__ void __launch_bounds__(256) init_maps()
{
    int i = blockIdx.x * 256 + threadIdx.x;
    if (i < MCELLS) g_map[i] = make_int4(INF_I, INF_I, INF_I, INF_I);
}

// AtomicMin cascade: slot0 = min row, slot1 = 2nd min, slot2 = 3rd min.
// Each value flows down, carrying the displaced (larger) row to the next slot.
__global__ void __launch_bounds__(256)
scatter_rows(const int* __restrict__ i0, const int* __restrict__ i1,
             const int* __restrict__ i2, const int* __restrict__ i3)
{
    int t = blockIdx.x * 256 + threadIdx.x;
    const int* inds; int g, base, row;
    if (t < 16000)      { inds = i0; g = 32; base = MB0; row = t; }
    else if (t < 20000) { inds = i1; g = 16; base = MB1; row = t - 16000; }
    else if (t < 20512) { inds = i2; g = 8;  base = MB2; row = t - 20000; }
    else if (t < 20576) { inds = i3; g = 4;  base = MB3; row = t - 20512; }
    else return;

    int4 v = ((const int4*)inds)[row];          // [batch, ix, iy, iz]
    int cell = (v.y * g + v.z) * g + v.w;
    int* s = (int*)&g_map[base + cell];
    int cur = row;
#pragma unroll
    for (int k = 0; k < 3; k++) {
        int old = atomicMin(&s[k], cur);
        cur = max(old, cur);                    // displaced value moves down
        if (cur == INF_I) break;
    }
}

// ---------------------------------------------------------------------------
__device__ __forceinline__ bool diless(float da, int ia, float db, int ib) {
    return (da < db) || (da == db && ia < ib);
}

__device__ __forceinline__ void ins3(float d, int i,
                                     float& d0, int& i0,
                                     float& d1, int& i1,
                                     float& d2, int& i2) {
    if (diless(d, i, d2, i2)) {
        d2 = d; i2 = i;
        if (diless(d2, i2, d1, i1)) { float td = d1; d1 = d2; d2 = td; int ti = i1; i1 = i2; i2 = ti; }
        if (diless(d1, i1, d0, i0)) { float td = d0; d0 = d1; d1 = td; int ti = i0; i0 = i1; i1 = ti; }
    }
}

// dedup-guarded insert (rows are globally unique keys) -> butterfly-safe merge
__device__ __forceinline__ void ins3d(float d, int i,
                                      float& d0, int& i0,
                                      float& d1, int& i1,
                                      float& d2, int& i2) {
    if (i != i0 && i != i1 && i != i2)
        ins3(d, i, d0, i0, d1, i1, d2, i2);
}

// ---------------------------------------------------------------------------
// One warp per (point, scale). task = point*4 + scale keeps blocks balanced.
// ---------------------------------------------------------------------------
__global__ void __launch_bounds__(256)
nn_gather(const float* __restrict__ pts,
          const float* __restrict__ f0, const float* __restrict__ f1,
          const float* __restrict__ f2, const float* __restrict__ f3,
          float* __restrict__ out)
{
    int warp  = (blockIdx.x * 256 + threadIdx.x) >> 5;
    int lane  = threadIdx.x & 31;
    int point = warp >> 2;
    int scale = warp & 3;

    const float* f; float vs; int g, base, C, coff;
    switch (scale) {
        case 0:  f = f0; vs = 0.015f * 2.0f;  g = 32; base = MB0; C = 32;  coff = 0;   break;
        case 1:  f = f1; vs = 0.015f * 4.0f;  g = 16; base = MB1; C = 64;  coff = 32;  break;
        case 2:  f = f2; vs = 0.015f * 8.0f;  g = 8;  base = MB2; C = 128; coff = 96;  break;
        default: f = f3; vs = 0.015f * 16.0f; g = 4;  base = MB3; C = 256; coff = 224; break;
    }
    const float OFF  = -0.48f;           // (-0.5*0.015f)*64 exactly as numpy f32
    const float HALF = 0.5f * vs;        // exact

    float px = pts[point * 3 + 0];
    float py = pts[point * 3 + 1];
    float pz = pts[point * 3 + 2];

    int cx = min(g - 1, max(0, (int)floorf((px - OFF) / vs)));
    int cy = min(g - 1, max(0, (int)floorf((py - OFF) / vs)));
    int cz = min(g - 1, max(0, (int)floorf((pz - OFF) / vs)));

    float d0 = CUDART_INF_F, d1 = CUDART_INF_F, d2 = CUDART_INF_F;
    int   r0 = INF_I,        r1 = INF_I,        r2 = INF_I;

    int rr = 1;
    bool first = true;
    while (true) {
        int side = 2 * rr + 1;
        int nc = side * side * side;
        for (int i = lane; i < nc; i += 32) {
            int t = i;
            int dz = t % side; t /= side;
            int dy = t % side;
            int dx = t / side;
            dx -= rr; dy -= rr; dz -= rr;
            if (!first) {  // interior (Chebyshev < rr) already examined
                int ch = max(max(abs(dx), abs(dy)), abs(dz));
                if (ch < rr) continue;
            }
            int jx = cx + dx, jy = cy + dy, jz = cz + dz;
            if ((unsigned)jx >= (unsigned)g || (unsigned)jy >= (unsigned)g ||
                (unsigned)jz >= (unsigned)g) continue;

            int4 s = g_map[base + (jx * g + jy) * g + jz];
            if (s.x == INF_I) continue;

            // voxel center, same op order as reference (no fma contraction)
            float qx = __fadd_rn(__fadd_rn(__fmul_rn((float)jx, vs), OFF), HALF);
            float qy = __fadd_rn(__fadd_rn(__fmul_rn((float)jy, vs), OFF), HALF);
            float qz = __fadd_rn(__fadd_rn(__fmul_rn((float)jz, vs), OFF), HALF);
            float ddx = px - qx, ddy = py - qy, ddz = pz - qz;
            float dd = __fadd_rn(__fadd_rn(__fmul_rn(ddx, ddx), __fmul_rn(ddy, ddy)),
                                 __fmul_rn(ddz, ddz));

            ins3(dd, s.x, d0, r0, d1, r1, d2, r2);
            if (s.y != INF_I) {
                ins3(dd, s.y, d0, r0, d1, r1, d2, r2);
                if (s.z != INF_I) ins3(dd, s.z, d0, r0, d1, r1, d2, r2);
            }
        }
        // conservative stop test: >=3 rows strictly inside the unexamined bound
        float b  = ((float)rr + 0.5f) * vs * 0.999999f;
        float b2 = b * b;
        int c = (int)(d0 < b2) + (int)(d1 < b2) + (int)(d2 < b2);
        int tot = __reduce_add_sync(0xffffffffu, c);
        if (tot >= 3) break;
        if (rr >= g) break;    // full grid examined -> result exact regardless
        rr++;
        first = false;
    }

    // butterfly merge (dedup-guarded: entries unique by row across lanes);
    // all lanes converge to the identical global top-3.
#pragma unroll
    for (int off = 16; off > 0; off >>= 1) {
        float e0 = __shfl_xor_sync(0xffffffffu, d0, off);
        float e1 = __shfl_xor_sync(0xffffffffu, d1, off);
        float e2 = __shfl_xor_sync(0xffffffffu, d2, off);
        int   j0 = __shfl_xor_sync(0xffffffffu, r0, off);
        int   j1 = __shfl_xor_sync(0xffffffffu, r1, off);
        int   j2 = __shfl_xor_sync(0xffffffffu, r2, off);
        ins3d(e0, j0, d0, r0, d1, r1, d2, r2);
        ins3d(e1, j1, d0, r0, d1, r1, d2, r2);
        ins3d(e2, j2, d0, r0, d1, r1, d2, r2);
    }

    float a0 = 1.0f / (d0 + 1e-8f);
    float a1 = 1.0f / (d1 + 1e-8f);
    float a2 = 1.0f / (d2 + 1e-8f);
    float inv = 1.0f / (a0 + a1 + a2);
    float w0 = a0 * inv, w1 = a1 * inv, w2 = a2 * inv;

    const float* p0 = f + (size_t)r0 * C;
    const float* p1 = f + (size_t)r1 * C;
    const float* p2 = f + (size_t)r2 * C;
    float* o = out + (size_t)point * OUTC + coff;
    for (int c = lane; c < C; c += 32)
        o[c] = w0 * p0[c] + w1 * p1[c] + w2 * p2[c];
}

// ---------------------------------------------------------------------------
// Inputs identified by element count (all ten distinct):
//   points 24576 | batch_ids 8192 (all-zero, unused by reference)
//   indices: 64000 / 16000 / 2048 / 256
//   feats:   512000 / 256000 / 65536 / 16384
// ---------------------------------------------------------------------------
extern "C" void kernel_launch(void* const* d_in, const int* in_sizes, int n_in,
                              void* d_out, int out_size)
{
    const float* points = nullptr;
    const int* idx[4] = {nullptr, nullptr, nullptr, nullptr};
    const float* feats[4] = {nullptr, nullptr, nullptr, nullptr};

    for (int i = 0; i < n_in; i++) {
        switch (in_sizes[i]) {
            case 24576:  points   = (const float*)d_in[i]; break;
            case 64000:  idx[0]   = (const int*)d_in[i];   break;
            case 16000:  idx[1]   = (const int*)d_in[i];   break;
            case 2048:   idx[2]   = (const int*)d_in[i];   break;
            case 256:    idx[3]   = (const int*)d_in[i];   break;
            case 512000: feats[0] = (const float*)d_in[i]; break;
            case 256000: feats[1] = (const float*)d_in[i]; break;
            case 65536:  feats[2] = (const float*)d_in[i]; break;
            case 16384:  feats[3] = (const float*)d_in[i]; break;
            default: break; // batch_ids unused
        }
    }

    init_maps<<<(MCELLS + 255) / 256, 256>>>();
    scatter_rows<<<(20576 + 255) / 256, 256>>>(idx[0], idx[1], idx[2], idx[3]);
    nn_gather<<<(4 * NPTS) / 8, 256>>>(points, feats[0], feats[1], feats[2], feats[3],
                                       (float*)d_out);
}

// round 5
// speedup vs baseline: 4.9240x; 1.2548x over previous
#include <cuda_runtime.h>
#include <math_constants.h>

// ---------------------------------------------------------------------------
// Exact 3-NN interpolation via grid ring-search — fully fused single kernel.
//   phase 0: init occupancy maps        (grid-strided)
//   phase 1: scatter rows (atomicMin cascade keeps 3 lowest rows per cell)
//   phase 2: per-(point,scale) warp ring-search + REDUX merge + f4 gather
// Grid barriers: sense-reversing, self-cleaning (safe across graph replays).
// Residency guarantee: 512 blocks, __launch_bounds__(256,4) -> >=4 blocks/SM
// co-resident on 148 SMs (592 slots), so spin barriers cannot deadlock.
//
// Tie-break correctness: duplicate voxel rows have bitwise-equal d2; per-cell
// slots are sorted by row, per-lane insertion and the REDUX merge are both
// (d2,row)-lexicographic, matching jax.lax.top_k's stable ordering. Distance
// math uses explicit __fmul_rn/__fadd_rn in the reference's op order (no fma
// contraction) — identical to the kernel that passed with rel_err 6e-8.
// ---------------------------------------------------------------------------

#define NPTS   8192
#define OUTC   480
#define INF_I  0x7fffffff
#define INF_FB 0x7f800000u

#define MB0 0
#define MB1 32768
#define MB2 (32768 + 4096)
#define MB3 (32768 + 4096 + 512)
#define MCELLS (32768 + 4096 + 512 + 64)

#define GRID   512
#define TPB    256
#define NWARPS (GRID * (TPB / 32))   // 4096
#define NTASKS (NPTS * 4)            // 32768 -> exactly 8 tasks per warp
#define NROWS  20576                 // 16000 + 4000 + 512 + 64

__device__ int4     g_map[MCELLS];
__device__ unsigned g_cnt[2];
__device__ unsigned g_phase[2];      // monotone sense counters; never reset

// Sense-reversing grid barrier. Only thread 0 of each block spins; phase
// counters persist across replays (count is reset by the completer).
__device__ __forceinline__ void grid_bar(int b)
{
    __syncthreads();
    if (threadIdx.x == 0) {
        volatile unsigned* ph = &g_phase[b];
        unsigned p0 = *ph;                   // sense observed before arriving
        __threadfence();                     // publish this block's writes
        unsigned prev = atomicAdd(&g_cnt[b], 1u);
        if (prev == GRID - 1) {
            g_cnt[b] = 0;                    // self-clean for next use
            __threadfence();
            *ph = p0 + 1u;                   // release
        } else {
            while (*ph == p0) { }
        }
        __threadfence();                     // acquire
    }
    __syncthreads();
}

__device__ __forceinline__ bool diless(float da, int ia, float db, int ib) {
    return (da < db) || (da == db && ia < ib);
}

__device__ __forceinline__ void ins3(float d, int i,
                                     float& d0, int& i0,
                                     float& d1, int& i1,
                                     float& d2, int& i2) {
    if (diless(d, i, d2, i2)) {
        d2 = d; i2 = i;
        if (diless(d2, i2, d1, i1)) { float td = d1; d1 = d2; d2 = td; int ti = i1; i1 = i2; i2 = ti; }
        if (diless(d1, i1, d0, i0)) { float td = d0; d0 = d1; d1 = td; int ti = i0; i0 = i1; i1 = ti; }
    }
}

// ---------------------------------------------------------------------------
__global__ void __launch_bounds__(TPB, 4)
fused(const float* __restrict__ pts,
      const int* __restrict__ x0, const int* __restrict__ x1,
      const int* __restrict__ x2, const int* __restrict__ x3,
      const float* __restrict__ f0, const float* __restrict__ f1,
      const float* __restrict__ f2, const float* __restrict__ f3,
      float* __restrict__ out)
{
    int gtid = blockIdx.x * TPB + threadIdx.x;

    // ---- phase 0: init occupancy maps ----
    for (int i = gtid; i < MCELLS; i += GRID * TPB)
        g_map[i] = make_int4(INF_I, INF_I, INF_I, INF_I);
    grid_bar(0);

    // ---- phase 1: scatter rows (3 lowest rows per cell, sorted) ----
    for (int t = gtid; t < NROWS; t += GRID * TPB) {
        const int* inds; int g, base, row;
        if (t < 16000)      { inds = x0; g = 32; base = MB0; row = t; }
        else if (t < 20000) { inds = x1; g = 16; base = MB1; row = t - 16000; }
        else if (t < 20512) { inds = x2; g = 8;  base = MB2; row = t - 20000; }
        else                { inds = x3; g = 4;  base = MB3; row = t - 20512; }
        int4 v = ((const int4*)inds)[row];           // [batch, ix, iy, iz]
        int* s = (int*)&g_map[base + (v.y * g + v.z) * g + v.w];
        int cur = row;
#pragma unroll
        for (int k = 0; k < 3; k++) {
            int old = atomicMin(&s[k], cur);
            cur = max(old, cur);                     // displaced value sinks
            if (cur == INF_I) break;
        }
    }
    grid_bar(1);

    // ---- phase 2: search + merge + gather, one warp per (point, scale) ----
    int warp = gtid >> 5;
    int lane = threadIdx.x & 31;
    const float OFF = -0.48f;                        // (-0.5*0.015f)*64, exact

#pragma unroll 1
    for (int task = warp; task < NTASKS; task += NWARPS) {
        int point = task >> 2, scale = task & 3;

        const float* f; float vs; int g, base, C4, coff;
        switch (scale) {
            case 0:  f = f0; vs = 0.015f * 2.0f;  g = 32; base = MB0; C4 = 8;  coff = 0;   break;
            case 1:  f = f1; vs = 0.015f * 4.0f;  g = 16; base = MB1; C4 = 16; coff = 32;  break;
            case 2:  f = f2; vs = 0.015f * 8.0f;  g = 8;  base = MB2; C4 = 32; coff = 96;  break;
            default: f = f3; vs = 0.015f * 16.0f; g = 4;  base = MB3; C4 = 64; coff = 224; break;
        }
        const float HALF = 0.5f * vs;

        float px = pts[point * 3 + 0];
        float py = pts[point * 3 + 1];
        float pz = pts[point * 3 + 2];

        int cx = min(g - 1, max(0, (int)floorf((px - OFF) / vs)));
        int cy = min(g - 1, max(0, (int)floorf((py - OFF) / vs)));
        int cz = min(g - 1, max(0, (int)floorf((pz - OFF) / vs)));

        float d0 = CUDART_INF_F, d1 = CUDART_INF_F, d2 = CUDART_INF_F;
        int   r0 = INF_I,        r1 = INF_I,        r2 = INF_I;

        int rr = 1;
        bool first = true;
        while (true) {
            int side = 2 * rr + 1;
            int nc = side * side * side;
            for (int i = lane; i < nc; i += 32) {
                int t = i;
                int dz = t % side; t /= side;
                int dy = t % side;
                int dx = t / side;
                dx -= rr; dy -= rr; dz -= rr;
                if (!first) {                        // interior already done
                    int ch = max(max(abs(dx), abs(dy)), abs(dz));
                    if (ch < rr) continue;
                }
                int jx = cx + dx, jy = cy + dy, jz = cz + dz;
                if ((unsigned)jx >= (unsigned)g || (unsigned)jy >= (unsigned)g ||
                    (unsigned)jz >= (unsigned)g) continue;

                int4 s = g_map[base + (jx * g + jy) * g + jz];
                if (s.x == INF_I) continue;

                float qx = __fadd_rn(__fadd_rn(__fmul_rn((float)jx, vs), OFF), HALF);
                float qy = __fadd_rn(__fadd_rn(__fmul_rn((float)jy, vs), OFF), HALF);
                float qz = __fadd_rn(__fadd_rn(__fmul_rn((float)jz, vs), OFF), HALF);
                float ddx = px - qx, ddy = py - qy, ddz = pz - qz;
                float dd = __fadd_rn(__fadd_rn(__fmul_rn(ddx, ddx), __fmul_rn(ddy, ddy)),
                                     __fmul_rn(ddz, ddz));

                ins3(dd, s.x, d0, r0, d1, r1, d2, r2);
                if (s.y != INF_I) {
                    ins3(dd, s.y, d0, r0, d1, r1, d2, r2);
                    if (s.z != INF_I) ins3(dd, s.z, d0, r0, d1, r1, d2, r2);
                }
            }
            // conservative stop: >=3 rows strictly inside unexamined bound
            float b  = ((float)rr + 0.5f) * vs * 0.999999f;
            float b2 = b * b;
            int c = (int)(d0 < b2) + (int)(d1 < b2) + (int)(d2 < b2);
            if (__reduce_add_sync(0xffffffffu, c) >= 3) break;
            if (rr >= g) break;                      // full grid -> exact
            rr++;
            first = false;
        }

        // ---- REDUX 3-way head merge (exact (d2,row) lexicographic) ----
        // Each lane's list is sorted, so the warp-global minimum is always a
        // current head. Rows are unique across lanes (each cell is visited by
        // exactly one lane), so the owner of each winner is unique.
        unsigned h0 = __float_as_uint(d0), h1 = __float_as_uint(d1),
                 h2 = __float_as_uint(d2);
        float wd[3]; int wr[3];
#pragma unroll
        for (int k = 0; k < 3; k++) {
            unsigned m  = __reduce_min_sync(0xffffffffu, h0);
            unsigned rm = __reduce_min_sync(0xffffffffu,
                              (h0 == m) ? (unsigned)r0 : (unsigned)INF_I);
            wd[k] = __uint_as_float(m); wr[k] = (int)rm;
            if (h0 == m && (unsigned)r0 == rm) {     // pop my head
                h0 = h1; r0 = r1; h1 = h2; r1 = r2; h2 = INF_FB; r2 = INF_I;
            }
        }

        float a0 = 1.0f / (wd[0] + 1e-8f);
        float a1 = 1.0f / (wd[1] + 1e-8f);
        float a2 = 1.0f / (wd[2] + 1e-8f);
        float inv = 1.0f / (a0 + a1 + a2);
        float w0 = a0 * inv, w1 = a1 * inv, w2 = a2 * inv;

        int C = C4 * 4;
        const float4* p0 = (const float4*)(f + (size_t)wr[0] * C);
        const float4* p1 = (const float4*)(f + (size_t)wr[1] * C);
        const float4* p2 = (const float4*)(f + (size_t)wr[2] * C);
        float4* o = (float4*)(out + (size_t)point * OUTC + coff);
        for (int c = lane; c < C4; c += 32) {
            float4 a = p0[c], b = p1[c], d = p2[c], r;
            r.x = w0 * a.x + w1 * b.x + w2 * d.x;
            r.y = w0 * a.y + w1 * b.y + w2 * d.y;
            r.z = w0 * a.z + w1 * b.z + w2 * d.z;
            r.w = w0 * a.w + w1 * b.w + w2 * d.w;
            o[c] = r;
        }
    }
}

// ---------------------------------------------------------------------------
// Inputs identified by element count (all ten distinct):
//   points 24576 | batch_ids 8192 (all-zero, unused by reference)
//   indices: 64000 / 16000 / 2048 / 256
//   feats:   512000 / 256000 / 65536 / 16384
// ---------------------------------------------------------------------------
extern "C" void kernel_launch(void* const* d_in, const int* in_sizes, int n_in,
                              void* d_out, int out_size)
{
    const float* points = nullptr;
    const int* idx[4] = {nullptr, nullptr, nullptr, nullptr};
    const float* feats[4] = {nullptr, nullptr, nullptr, nullptr};

    for (int i = 0; i < n_in; i++) {
        switch (in_sizes[i]) {
            case 24576:  points   = (const float*)d_in[i]; break;
            case 64000:  idx[0]   = (const int*)d_in[i];   break;
            case 16000:  idx[1]   = (const int*)d_in[i];   break;
            case 2048:   idx[2]   = (const int*)d_in[i];   break;
            case 256:    idx[3]   = (const int*)d_in[i];   break;
            case 512000: feats[0] = (const float*)d_in[i]; break;
            case 256000: feats[1] = (const float*)d_in[i]; break;
            case 65536:  feats[2] = (const float*)d_in[i]; break;
            case 16384:  feats[3] = (const float*)d_in[i]; break;
            default: break; // batch_ids unused
        }
    }

    fused<<<GRID, TPB>>>(points, idx[0], idx[1], idx[2], idx[3],
                         feats[0], feats[1], feats[2], feats[3],
                         (float*)d_out);
}

// round 7
// speedup vs baseline: 6.0389x; 1.2264x over previous
#include <cuda_runtime.h>
#include <math_constants.h>

// ---------------------------------------------------------------------------
// Exact 3-NN interpolation via grid ring-search — fully fused single kernel.
//   phase 0: init occupancy maps        (grid-strided)
//   phase 1: scatter rows (atomicMin cascade keeps 3 lowest rows per cell)
//   phase 2: per-(point,scale) warp ring-search + REDUX merge + f4 gather
// Grid barriers: sense-reversing, self-cleaning (safe across graph replays).
// Residency: GRID=740 = 5 blocks/SM x 148 SMs, __launch_bounds__(256,5)
// guarantees all blocks co-resident -> spin barrier cannot deadlock.
// Reg cap at 5 blocks/SM is 51 >= 47 currently used -> no spill regression.
//
// Tie-break correctness: duplicate voxel rows have bitwise-equal d2; per-cell
// slots are sorted by row, per-lane insertion and the REDUX merge are both
// (d2,row)-lexicographic, matching jax.lax.top_k's stable ordering. Distance
// math uses explicit __fmul_rn/__fadd_rn in the reference's op order (no fma
// contraction) — identical to the kernel that passed with rel_err 6e-8.
// ---------------------------------------------------------------------------

#define NPTS   8192
#define OUTC   480
#define INF_I  0x7fffffff
#define INF_FB 0x7f800000u

#define MB0 0
#define MB1 32768
#define MB2 (32768 + 4096)
#define MB3 (32768 + 4096 + 512)
#define MCELLS (32768 + 4096 + 512 + 64)

#define GRID   740                   // 5 blocks/SM * 148 SMs, all resident
#define TPB    256
#define NWARPS (GRID * (TPB / 32))   // 5920
#define NTASKS (NPTS * 4)            // 32768
#define NROWS  20576                 // 16000 + 4000 + 512 + 64

__device__ int4     g_map[MCELLS];
__device__ unsigned g_cnt[2];
__device__ unsigned g_phase[2];      // monotone sense counters; never reset

// Sense-reversing grid barrier. Only thread 0 of each block spins; phase
// counters persist across replays (count is reset by the completer).
__device__ __forceinline__ void grid_bar(int b)
{
    __syncthreads();
    if (threadIdx.x == 0) {
        volatile unsigned* ph = &g_phase[b];
        unsigned p0 = *ph;                   // sense observed before arriving
        __threadfence();                     // publish this block's writes
        unsigned prev = atomicAdd(&g_cnt[b], 1u);
        if (prev == GRID - 1) {
            g_cnt[b] = 0;                    // self-clean for next use
            __threadfence();
            *ph = p0 + 1u;                   // release
        } else {
            while (*ph == p0) { }
        }
        __threadfence();                     // acquire
    }
    __syncthreads();
}

__device__ __forceinline__ bool diless(float da, int ia, float db, int ib) {
    return (da < db) || (da == db && ia < ib);
}

__device__ __forceinline__ void ins3(float d, int i,
                                     float& d0, int& i0,
                                     float& d1, int& i1,
                                     float& d2, int& i2) {
    if (diless(d, i, d2, i2)) {
        d2 = d; i2 = i;
        if (diless(d2, i2, d1, i1)) { float td = d1; d1 = d2; d2 = td; int ti = i1; i1 = i2; i2 = ti; }
        if (diless(d1, i1, d0, i0)) { float td = d0; d0 = d1; d1 = td; int ti = i0; i0 = i1; i1 = ti; }
    }
}

// Examine one cell (jx,jy,jz): bounds check, map lookup, distance, insert.
__device__ __forceinline__ void visit_cell(
    int jx, int jy, int jz, int g, int base,
    float vs, float OFF, float HALF,
    float px, float py, float pz,
    float& d0, int& r0, float& d1, int& r1, float& d2, int& r2)
{
    if ((unsigned)jx >= (unsigned)g || (unsigned)jy >= (unsigned)g ||
        (unsigned)jz >= (unsigned)g) return;

    int4 s = g_map[base + (jx * g + jy) * g + jz];
    if (s.x == INF_I) return;

    // voxel center, same op order as reference (no fma contraction)
    float qx = __fadd_rn(__fadd_rn(__fmul_rn((float)jx, vs), OFF), HALF);
    float qy = __fadd_rn(__fadd_rn(__fmul_rn((float)jy, vs), OFF), HALF);
    float qz = __fadd_rn(__fadd_rn(__fmul_rn((float)jz, vs), OFF), HALF);
    float ddx = px - qx, ddy = py - qy, ddz = pz - qz;
    float dd = __fadd_rn(__fadd_rn(__fmul_rn(ddx, ddx), __fmul_rn(ddy, ddy)),
                         __fmul_rn(ddz, ddz));

    ins3(dd, s.x, d0, r0, d1, r1, d2, r2);
    if (s.y != INF_I) {
        ins3(dd, s.y, d0, r0, d1, r1, d2, r2);
        if (s.z != INF_I) ins3(dd, s.z, d0, r0, d1, r1, d2, r2);
    }
}

// Warp-wide stop test: >=3 candidate rows strictly inside the bound that no
// unexamined cell can beat. Conservative (0.999999 shrink), hence exact.
__device__ __forceinline__ bool stop_ok(int rr, float vs,
                                        float d0, float d1, float d2)
{
    float b  = ((float)rr + 0.5f) * vs * 0.999999f;
    float b2 = b * b;
    int c = (int)(d0 < b2) + (int)(d1 < b2) + (int)(d2 < b2);
    return __reduce_add_sync(0xffffffffu, c) >= 3;
}

// ---------------------------------------------------------------------------
__global__ void __launch_bounds__(TPB, 5)
fused(const float* __restrict__ pts,
      const int* __restrict__ x0, const int* __restrict__ x1,
      const int* __restrict__ x2, const int* __restrict__ x3,
      const float* __restrict__ f0, const float* __restrict__ f1,
      const float* __restrict__ f2, const float* __restrict__ f3,
      float* __restrict__ out)
{
    int gtid = blockIdx.x * TPB + threadIdx.x;

    // ---- phase 0: init occupancy maps ----
    for (int i = gtid; i < MCELLS; i += GRID * TPB)
        g_map[i] = make_int4(INF_I, INF_I, INF_I, INF_I);
    grid_bar(0);

    // ---- phase 1: scatter rows (3 lowest rows per cell, sorted) ----
    for (int t = gtid; t < NROWS; t += GRID * TPB) {
        const int* inds; int g, base, row;
        if (t < 16000)      { inds = x0; g = 32; base = MB0; row = t; }
        else if (t < 20000) { inds = x1; g = 16; base = MB1; row = t - 16000; }
        else if (t < 20512) { inds = x2; g = 8;  base = MB2; row = t - 20000; }
        else                { inds = x3; g = 4;  base = MB3; row = t - 20512; }
        int4 v = ((const int4*)inds)[row];           // [batch, ix, iy, iz]
        int* s = (int*)&g_map[base + (v.y * g + v.z) * g + v.w];
        int cur = row;
#pragma unroll
        for (int k = 0; k < 3; k++) {
            int old = atomicMin(&s[k], cur);
            cur = max(old, cur);                     // displaced value sinks
            if (cur == INF_I) break;
        }
    }
    grid_bar(1);

    // ---- phase 2: search + merge + gather, one warp per (point, scale) ----
    int warp = gtid >> 5;
    int lane = threadIdx.x & 31;
    const float OFF = -0.48f;                        // (-0.5*0.015f)*64, exact

#pragma unroll 1
    for (int task = warp; task < NTASKS; task += NWARPS) {
        int point = task >> 2, scale = task & 3;

        const float* f; float vs; int g, base, C4, coff;
        switch (scale) {
            case 0:  f = f0; vs = 0.015f * 2.0f;  g = 32; base = MB0; C4 = 8;  coff = 0;   break;
            case 1:  f = f1; vs = 0.015f * 4.0f;  g = 16; base = MB1; C4 = 16; coff = 32;  break;
            case 2:  f = f2; vs = 0.015f * 8.0f;  g = 8;  base = MB2; C4 = 32; coff = 96;  break;
            default: f = f3; vs = 0.015f * 16.0f; g = 4;  base = MB3; C4 = 64; coff = 224; break;
        }
        const float HALF = 0.5f * vs;

        float px = __ldg(&pts[point * 3 + 0]);
        float py = __ldg(&pts[point * 3 + 1]);
        float pz = __ldg(&pts[point * 3 + 2]);

        int cx = min(g - 1, max(0, (int)floorf((px - OFF) / vs)));
        int cy = min(g - 1, max(0, (int)floorf((py - OFF) / vs)));
        int cz = min(g - 1, max(0, (int)floorf((pz - OFF) / vs)));

        float d0 = CUDART_INF_F, d1 = CUDART_INF_F, d2 = CUDART_INF_F;
        int   r0 = INF_I,        r1 = INF_I,        r2 = INF_I;

        // ---- specialized rr=1 ring: 27 cells, lanes 0..26, no decode loop ----
        if (lane < 27) {
            int dz = lane % 3 - 1;
            int r3 = lane / 3;
            int dy = r3 % 3 - 1;
            int dx = r3 / 3 - 1;
            visit_cell(cx + dx, cy + dy, cz + dz, g, base, vs, OFF, HALF,
                       px, py, pz, d0, r0, d1, r1, d2, r2);
        }

        if (!stop_ok(1, vs, d0, d1, d2)) {
            // ---- general shell rings rr >= 2 (uncommon path) ----
            int rr = 2;
            while (rr <= g) {
                int side = 2 * rr + 1;
                int nc = side * side * side;
                for (int i = lane; i < nc; i += 32) {
                    int t = i;
                    int dz = t % side; t /= side;
                    int dy = t % side;
                    int dx = t / side;
                    dx -= rr; dy -= rr; dz -= rr;
                    int ch = max(max(abs(dx), abs(dy)), abs(dz));
                    if (ch < rr) continue;           // interior already done
                    visit_cell(cx + dx, cy + dy, cz + dz, g, base, vs, OFF, HALF,
                               px, py, pz, d0, r0, d1, r1, d2, r2);
                }
                if (stop_ok(rr, vs, d0, d1, d2)) break;
                if (rr >= g) break;                  // full grid -> exact
                rr++;
            }
        }

        // ---- REDUX 3-way head merge (exact (d2,row) lexicographic) ----
        // Each lane's list is sorted, so the warp-global minimum is always a
        // current head. Rows are unique across lanes (each cell is visited by
        // exactly one lane), so the owner of each winner is unique.
        unsigned h0 = __float_as_uint(d0), h1 = __float_as_uint(d1),
                 h2 = __float_as_uint(d2);
        float wd[3]; int wr[3];
#pragma unroll
        for (int k = 0; k < 3; k++) {
            unsigned m  = __reduce_min_sync(0xffffffffu, h0);
            unsigned rm = __reduce_min_sync(0xffffffffu,
                              (h0 == m) ? (unsigned)r0 : (unsigned)INF_I);
            wd[k] = __uint_as_float(m); wr[k] = (int)rm;
            if (h0 == m && (unsigned)r0 == rm) {     // pop my head
                h0 = h1; r0 = r1; h1 = h2; r1 = r2; h2 = INF_FB; r2 = INF_I;
            }
        }

        float a0 = 1.0f / (wd[0] + 1e-8f);
        float a1 = 1.0f / (wd[1] + 1e-8f);
        float a2 = 1.0f / (wd[2] + 1e-8f);
        float inv = 1.0f / (a0 + a1 + a2);
        float w0 = a0 * inv, w1 = a1 * inv, w2 = a2 * inv;

        int C = C4 * 4;
        const float4* p0 = (const float4*)(f + (size_t)wr[0] * C);
        const float4* p1 = (const float4*)(f + (size_t)wr[1] * C);
        const float4* p2 = (const float4*)(f + (size_t)wr[2] * C);
        float4* o = (float4*)(out + (size_t)point * OUTC + coff);
        for (int c = lane; c < C4; c += 32) {
            float4 a = p0[c], b = p1[c], d = p2[c], r;
            r.x = w0 * a.x + w1 * b.x + w2 * d.x;
            r.y = w0 * a.y + w1 * b.y + w2 * d.y;
            r.z = w0 * a.z + w1 * b.z + w2 * d.z;
            r.w = w0 * a.w + w1 * b.w + w2 * d.w;
            o[c] = r;
        }
    }
}

// ---------------------------------------------------------------------------
// Inputs identified by element count (all ten distinct):
//   points 24576 | batch_ids 8192 (all-zero, unused by reference)
//   indices: 64000 / 16000 / 2048 / 256
//   feats:   512000 / 256000 / 65536 / 16384
// ---------------------------------------------------------------------------
extern "C" void kernel_launch(void* const* d_in, const int* in_sizes, int n_in,
                              void* d_out, int out_size)
{
    const float* points = nullptr;
    const int* idx[4] = {nullptr, nullptr, nullptr, nullptr};
    const float* feats[4] = {nullptr, nullptr, nullptr, nullptr};

    for (int i = 0; i < n_in; i++) {
        switch (in_sizes[i]) {
            case 24576:  points   = (const float*)d_in[i]; break;
            case 64000:  idx[0]   = (const int*)d_in[i];   break;
            case 16000:  idx[1]   = (const int*)d_in[i];   break;
            case 2048:   idx[2]   = (const int*)d_in[i];   break;
            case 256:    idx[3]   = (const int*)d_in[i];   break;
            case 512000: feats[0] = (const float*)d_in[i]; break;
            case 256000: feats[1] = (const float*)d_in[i]; break;
            case 65536:  feats[2] = (const float*)d_in[i]; break;
            case 16384:  feats[3] = (const float*)d_in[i]; break;
            default: break; // batch_ids unused
        }
    }

    fused<<<GRID, TPB>>>(points, idx[0], idx[1], idx[2], idx[3],
                         feats[0], feats[1], feats[2], feats[3],
                         (float*)d_out);
}